// round 7
// baseline (speedup 1.0000x reference)
#include <cuda_runtime.h>
#include <cuda_bf16.h>
#include <math.h>

#define BB 32
#define HID 2048
#define INNER 4096
#define NH 8
#define HEAD 512
#define K3 12288
#define CAP 30.0f
#define EPS 1e-6f
#define GN_EPS 1e-5f
#define KSCALE 0.044194173824159216f   // 1/sqrt(512)

// ---------------- scratch (device globals; no allocs allowed) ----------------
__device__ float g_xn   [BB * HID];
__device__ float g_xmc  [BB * INNER];
__device__ float g_qkv  [BB * K3];
__device__ float g_h    [BB * INNER];
__device__ float g_part [16 * BB * K3];            // split-K partials
__device__ float g_numer[BB * NH * 4 * HEAD];      // cell numer partials
__device__ float g_ig   [BB * NH];
__device__ float g_fg   [BB * NH];

// ---------------- output layout ----------------
#define Y_OFF    0
#define CONV_OFF 65536
#define CELL_OFF 458752
#define NORM_OFF 67567616
#define MAX_OFF  67698688

// ---------------- helpers ----------------
__device__ __forceinline__ void fma2(unsigned long long& d,
                                     unsigned long long a,
                                     unsigned long long b)
{
    asm("fma.rn.f32x2 %0, %1, %2, %0;" : "+l"(d) : "l"(a), "l"(b));
}
union U64F2 { unsigned long long u; float2 f; };

__device__ __forceinline__ void cp16(void* smem, const void* g)
{
    unsigned s = (unsigned)__cvta_generic_to_shared(smem);
    asm volatile("cp.async.cg.shared.global [%0], [%1], 16;\n" :: "r"(s), "l"(g));
}

// ============================================================================
// 1) RMSNorm
// ============================================================================
__global__ void rmsnorm_kernel(const float* __restrict__ x,
                               const float* __restrict__ rms_w)
{
    __shared__ float red[256];
    int b = blockIdx.x;
    int tid = threadIdx.x;
    const float* xr = x + b * HID;
    float s = 0.f;
    for (int i = tid; i < HID; i += 256) { float v = xr[i]; s += v * v; }
    red[tid] = s; __syncthreads();
    for (int st = 128; st > 0; st >>= 1) {
        if (tid < st) red[tid] += red[tid + st];
        __syncthreads();
    }
    float rstd = rsqrtf(red[0] / (float)HID + EPS);
    float* o = g_xn + b * HID;
    for (int i = tid; i < HID; i += 256) o[i] = xr[i] * rstd * rms_w[i];
}

// ============================================================================
// 2) GEMM: C[32,N] = A[32,K] @ W[N,K]^T, uneven split-K partials.
//    BM=32, BN=256, BK=16, 256 threads, thread tile 8m x 4n, fma2 k-dots,
//    cp.async k-major tiles (no transpose). Dual-W via nb1.
// ============================================================================
__global__ __launch_bounds__(256, 3) void gemm_v2(
    const float* __restrict__ A,
    const float* __restrict__ W1, float* __restrict__ C1,
    const float* __restrict__ W2, float* __restrict__ C2,
    int nb1, int N, int Kt)
{
    __shared__ __align__(16) float As[2][32][20];
    __shared__ __align__(16) float Ws[2][256][20];

    const int bx = blockIdx.x;
    const float* W = (bx < nb1) ? W1 : W2;
    float* C = ((bx < nb1) ? C1 : C2) + (size_t)blockIdx.y * 32 * N;
    const int n0 = ((bx < nb1) ? bx : bx - nb1) * 256;

    // uneven k-split over 16-wide tiles
    const int TT = Kt >> 4;
    const int G = gridDim.y;
    const int base = TT / G;
    const int rem = TT - base * G;
    const int by = blockIdx.y;
    const int tBeg = by * base + (by < rem ? by : rem);
    const int T = base + (by < rem ? 1 : 0);
    const int kBeg = tBeg << 4;

    const int t = threadIdx.x;
    const int tn = t & 63;
    const int tm = t >> 6;

    const float* wsrc = W + (size_t)(n0 + t) * Kt + kBeg;
    const float* asrc = A + (size_t)(t >> 2) * Kt + kBeg + (t & 3) * 4;

    unsigned long long acc[8][4];
    #pragma unroll
    for (int i = 0; i < 8; i++)
        #pragma unroll
        for (int j = 0; j < 4; j++) acc[i][j] = 0ull;

    {
        #pragma unroll
        for (int k4 = 0; k4 < 4; k4++)
            cp16(&Ws[0][t][k4*4], wsrc + k4*4);
        if (t < 128)
            cp16(&As[0][t>>2][(t&3)*4], asrc);
        asm volatile("cp.async.commit_group;\n");
    }

    for (int tile = 0; tile < T; tile++) {
        const int cur = tile & 1;
        const int nxt = cur ^ 1;
        if (tile + 1 < T) {
            const float* ws = wsrc + (tile + 1) * 16;
            #pragma unroll
            for (int k4 = 0; k4 < 4; k4++)
                cp16(&Ws[nxt][t][k4*4], ws + k4*4);
            if (t < 128)
                cp16(&As[nxt][t>>2][(t&3)*4], asrc + (tile + 1) * 16);
            asm volatile("cp.async.commit_group;\n");
            asm volatile("cp.async.wait_group 1;\n");
        } else {
            asm volatile("cp.async.wait_group 0;\n");
        }
        __syncthreads();

        #pragma unroll
        for (int k4 = 0; k4 < 4; k4++) {
            ulonglong2 a[8];
            #pragma unroll
            for (int i = 0; i < 8; i++)
                a[i] = *(const ulonglong2*)&As[cur][tm*8 + i][k4*4];
            #pragma unroll
            for (int j = 0; j < 4; j++) {
                ulonglong2 w = *(const ulonglong2*)&Ws[cur][j*64 + tn][k4*4];
                #pragma unroll
                for (int i = 0; i < 8; i++) {
                    fma2(acc[i][j], a[i].x, w.x);
                    fma2(acc[i][j], a[i].y, w.y);
                }
            }
        }
        __syncthreads();
    }

    #pragma unroll
    for (int i = 0; i < 8; i++) {
        float* cr = C + (size_t)(tm*8 + i) * N + n0;
        #pragma unroll
        for (int j = 0; j < 4; j++) {
            U64F2 u; u.u = acc[i][j];
            cr[j*64 + tn] = u.f.x + u.f.y;
        }
    }
}

// ============================================================================
// 3) Templated split-K reduce: C = sum_s part[s] (+ addv)
// ============================================================================
template<int S>
__global__ void reduce_split_t(const float* __restrict__ part, int elems,
                               const float* __restrict__ addv,
                               float* __restrict__ C)
{
    int i = blockIdx.x * blockDim.x + threadIdx.x;
    const float4* p = (const float4*)part;
    int q = elems >> 2;
    float4 s = p[i];
    #pragma unroll
    for (int j = 1; j < S; j++) {
        float4 t = p[i + (size_t)j * q];
        s.x += t.x; s.y += t.y; s.z += t.z; s.w += t.w;
    }
    if (addv) {
        float4 a = ((const float4*)addv)[i];
        s.x += a.x; s.y += a.y; s.z += a.z; s.w += a.w;
    }
    ((float4*)C)[i] = s;
}

// ============================================================================
// 4) Conv + fused xm split-reduce + silu + new_conv_state
// ============================================================================
__global__ void conv_kernel(const float* __restrict__ conv_state,
                            const float* __restrict__ conv_w,
                            const float* __restrict__ conv_b,
                            const float* __restrict__ xm_part,
                            float* __restrict__ out)
{
    int idx = blockIdx.x * blockDim.x + threadIdx.x;
    if (idx >= BB * INNER) return;
    int c = idx & (INNER - 1);
    float xm = 0.f;
    #pragma unroll
    for (int s = 0; s < 8; s++) xm += xm_part[(size_t)s * BB * INNER + idx];
    const float* cs = conv_state + (size_t)idx * 3;
    float s0 = cs[0], s1 = cs[1], s2 = cs[2];
    const float* w = conv_w + c * 4;
    float xc = s0*w[0] + s1*w[1] + s2*w[2] + xm*w[3] + conv_b[c];
    float* nc = out + CONV_OFF + (size_t)idx * 3;
    nc[0] = s1; nc[1] = s2; nc[2] = xm;
    g_xmc[idx] = xc / (1.f + expf(-xc));
}

// ============================================================================
// 5) Gates
// ============================================================================
__global__ __launch_bounds__(256) void gate_kernel(
    const float* __restrict__ Wi, const float* __restrict__ bi,
    const float* __restrict__ Wf, const float* __restrict__ bf,
    const float* __restrict__ max_state,
    float* __restrict__ out)
{
    __shared__ float ri[256], rf[256];
    int bh = blockIdx.x;
    int h = bh & (NH - 1);
    int b = bh >> 3;
    int tid = threadIdx.x;
    const float4* q4  = (const float4*)(g_qkv + (size_t)b * K3);
    const float4* wi4 = (const float4*)(Wi + (size_t)h * K3);
    const float4* wf4 = (const float4*)(Wf + (size_t)h * K3);
    float si = 0.f, sf = 0.f;
    #pragma unroll
    for (int r = 0; r < K3/4/256; r++) {
        int j = tid + r * 256;
        float4 q = q4[j], a = wi4[j], f = wf4[j];
        si += q.x*a.x + q.y*a.y + q.z*a.z + q.w*a.w;
        sf += q.x*f.x + q.y*f.y + q.z*f.z + q.w*f.w;
    }
    ri[tid] = si; rf[tid] = sf; __syncthreads();
    for (int st = 128; st > 0; st >>= 1) {
        if (tid < st) { ri[tid] += ri[tid+st]; rf[tid] += rf[tid+st]; }
        __syncthreads();
    }
    if (tid == 0) {
        float ig = CAP * tanhf((ri[0] + bi[h]) / CAP);
        float fg = CAP * tanhf((rf[0] + bf[h]) / CAP);
        float lf = (fg >= 0.f) ? -log1pf(expf(-fg)) : (fg - log1pf(expf(fg)));
        float m_old = max_state[bh];
        float m_new = fmaxf(ig, m_old + lf);
        g_ig[bh] = expf(ig - m_new);
        g_fg[bh] = expf(lf + m_old - m_new);
        out[MAX_OFF + bh] = m_new;
    }
}

// ============================================================================
// 6) Cell stream: grid = 4 chunks x 256 bh; 256 threads.
// ============================================================================
__global__ __launch_bounds__(256) void cell_stream(
    const float* __restrict__ cell_state,
    float* __restrict__ out)
{
    __shared__ float qsm[128], ksm[128];
    __shared__ float part[2][HEAD];

    const int bid = blockIdx.x;
    const int bh = bid >> 2;
    const int ch = bid & 3;
    const int h = bh & (NH - 1);
    const int b = bh >> 3;
    const int tid = threadIdx.x;

    const float* qrow = g_qkv + (size_t)b * K3 + h * HEAD;
    const float* krow = qrow + INNER;
    const float* vrow = qrow + 2 * INNER;
    const int d0 = ch * 128;

    if (tid < 128) {
        qsm[tid] = qrow[d0 + tid];
        ksm[tid] = krow[d0 + tid] * KSCALE;
    }
    __syncthreads();

    const float ig = g_ig[bh];
    const float fg = g_fg[bh];

    const int ct = tid & 127;
    const int rg = tid >> 7;
    const int e0 = ct * 4;
    float4 v = *(const float4*)(vrow + e0);
    float4 iv = make_float4(ig*v.x, ig*v.y, ig*v.z, ig*v.w);

    const float* cin  = cell_state + (size_t)bh * HEAD * HEAD;
    float*       cout = out + CELL_OFF + (size_t)bh * HEAD * HEAD;

    float4 nacc = make_float4(0.f, 0.f, 0.f, 0.f);
    #pragma unroll 8
    for (int dd = rg; dd < 128; dd += 2) {
        int d = d0 + dd;
        float4 cv = *(const float4*)(cin + (size_t)d * HEAD + e0);
        float kd = ksm[dd];
        float4 c;
        c.x = fmaf(fg, cv.x, kd * iv.x);
        c.y = fmaf(fg, cv.y, kd * iv.y);
        c.z = fmaf(fg, cv.z, kd * iv.z);
        c.w = fmaf(fg, cv.w, kd * iv.w);
        *(float4*)(cout + (size_t)d * HEAD + e0) = c;
        float qd = qsm[dd];
        nacc.x = fmaf(qd, c.x, nacc.x);
        nacc.y = fmaf(qd, c.y, nacc.y);
        nacc.z = fmaf(qd, c.z, nacc.z);
        nacc.w = fmaf(qd, c.w, nacc.w);
    }
    *(float4*)&part[rg][e0] = nacc;
    __syncthreads();
    if (tid < 128) {
        float4 p0 = *(const float4*)&part[0][e0];
        float4 p1 = *(const float4*)&part[1][e0];
        float4 s = make_float4(p0.x+p1.x, p0.y+p1.y, p0.z+p1.z, p0.w+p1.w);
        *(float4*)(g_numer + (size_t)bid * HEAD + e0) = s;
    }
}

// ============================================================================
// 7) Cell epilogue: norm_new + qn + denom + GroupNorm + gating -> h
//    (x_gate split-K reduce fused in: sums 8 partials inline)
// ============================================================================
__global__ __launch_bounds__(512) void cell_epi(
    const float* __restrict__ norm_state,
    const float* __restrict__ gn_w, const float* __restrict__ gn_b,
    const float* __restrict__ skip_w,
    const float* __restrict__ xg_part,
    float* __restrict__ out)
{
    __shared__ float red[512];
    const int bh = blockIdx.x;
    const int h = bh & (NH - 1);
    const int b = bh >> 3;
    const int tid = threadIdx.x;

    const float* qrow = g_qkv + (size_t)b * K3 + h * HEAD;
    const float* krow = qrow + INNER;
    float q = qrow[tid];
    float k = krow[tid] * KSCALE;

    const float ig = g_ig[bh];
    const float fg = g_fg[bh];
    const float m_new = out[MAX_OFF + bh];

    float num = g_numer[(size_t)(bh*4+0) * HEAD + tid]
              + g_numer[(size_t)(bh*4+1) * HEAD + tid]
              + g_numer[(size_t)(bh*4+2) * HEAD + tid]
              + g_numer[(size_t)(bh*4+3) * HEAD + tid];

    float nn = fmaf(fg, norm_state[(size_t)bh * HEAD + tid], ig * k);
    out[NORM_OFF + (size_t)bh * HEAD + tid] = nn;

    red[tid] = q * nn; __syncthreads();
    for (int st = 256; st > 0; st >>= 1) {
        if (tid < st) red[tid] += red[tid+st];
        __syncthreads();
    }
    float qn = red[0]; __syncthreads();
    float denom = fmaxf(fabsf(qn), expf(-m_new)) + EPS;
    float o = num / denom;

    red[tid] = o; __syncthreads();
    for (int st = 256; st > 0; st >>= 1) {
        if (tid < st) red[tid] += red[tid+st];
        __syncthreads();
    }
    float mu = red[0] / (float)HEAD; __syncthreads();
    float dv = o - mu;
    red[tid] = dv * dv; __syncthreads();
    for (int st = 256; st > 0; st >>= 1) {
        if (tid < st) red[tid] += red[tid+st];
        __syncthreads();
    }
    float rstd = rsqrtf(red[0] / (float)HEAD + GN_EPS);

    int c = h * HEAD + tid;
    size_t gidx = (size_t)b * INNER + c;
    // fused x_gate split-K reduce
    float xg = 0.f;
    #pragma unroll
    for (int s = 0; s < 8; s++) xg += xg_part[(size_t)s * BB * INNER + gidx];
    float og = fmaf(dv * rstd, gn_w[c], gn_b[c]);
    float sg = xg / (1.f + expf(-xg));
    g_h[gidx] = (og + skip_w[c] * g_xmc[gidx]) * sg;
}

// ============================================================================
extern "C" void kernel_launch(void* const* d_in, const int* in_sizes, int n_in,
                              void* d_out, int out_size)
{
    const float* x          = (const float*)d_in[0];
    const float* conv_state = (const float*)d_in[1];
    const float* cell_state = (const float*)d_in[2];
    const float* norm_state = (const float*)d_in[3];
    const float* max_state  = (const float*)d_in[4];
    const float* rms_w      = (const float*)d_in[5];
    const float* Wx         = (const float*)d_in[6];
    const float* Wg         = (const float*)d_in[7];
    const float* Wqkv       = (const float*)d_in[8];
    const float* conv_w     = (const float*)d_in[9];
    const float* conv_b     = (const float*)d_in[10];
    const float* Wi         = (const float*)d_in[11];
    const float* bi         = (const float*)d_in[12];
    const float* Wf         = (const float*)d_in[13];
    const float* bf         = (const float*)d_in[14];
    const float* gn_w       = (const float*)d_in[15];
    const float* gn_b       = (const float*)d_in[16];
    const float* Wdown      = (const float*)d_in[17];
    const float* skip_w     = (const float*)d_in[18];
    float* out = (float*)d_out;

    float* pxn;   cudaGetSymbolAddress((void**)&pxn,   g_xn);
    float* pxmc;  cudaGetSymbolAddress((void**)&pxmc,  g_xmc);
    float* pqkv;  cudaGetSymbolAddress((void**)&pqkv,  g_qkv);
    float* ph;    cudaGetSymbolAddress((void**)&ph,    g_h);
    float* ppart; cudaGetSymbolAddress((void**)&ppart, g_part);

    // Wg partials live in the UPPER half of g_part so the QKV GEMM
    // (which writes [0, 6*BB*K3)) cannot clobber them before cell_epi reads.
    float* pp2 = ppart + (size_t)8 * BB * K3;

    // 1) rmsnorm
    rmsnorm_kernel<<<BB, 256>>>(x, rms_w);

    // 2) x_mlstm & x_gate fused, split-K 8: grid (16+16, 8) = 256 blocks
    gemm_v2<<<dim3(32, 8), 256>>>(pxn, Wx, ppart, Wg, pp2, 16, INNER, HID);

    // 3) conv + fused xm reduce + silu + new_conv_state
    conv_kernel<<<(BB*INNER)/256, 256>>>(conv_state, conv_w, conv_b, ppart, out);

    // 4) qkv = xmc @ Wqkv^T, uneven split-K 6: grid (48, 6) = 288 blocks
    gemm_v2<<<dim3(48, 6), 256>>>(pxmc, Wqkv, ppart, nullptr, nullptr,
                                  48, K3, INNER);
    reduce_split_t<6><<<(BB*K3/4)/256, 256>>>(ppart, BB*K3, nullptr, pqkv);

    // 5) gates
    gate_kernel<<<BB*NH, 256>>>(Wi, bi, Wf, bf, max_state, out);

    // 6) cell stream: 1024 blocks, one wave
    cell_stream<<<BB*NH*4, 256>>>(cell_state, out);

    // 7) cell epilogue (x_gate reduce fused) -> h
    cell_epi<<<BB*NH, 512>>>(norm_state, gn_w, gn_b, skip_w, pp2, out);

    // 8) y = h @ Wdown^T + x, split-K 32: grid (8, 32) = 256 blocks
    gemm_v2<<<dim3(8, 32), 256>>>(ph, Wdown, ppart, nullptr, nullptr,
                                  8, HID, INNER);
    reduce_split_t<32><<<(BB*HID/4)/256, 256>>>(ppart, BB*HID, x, out + Y_OFF);
}

// round 9
// speedup vs baseline: 1.1410x; 1.1410x over previous
#include <cuda_runtime.h>
#include <cuda_bf16.h>
#include <math.h>
#include <stdint.h>

#define BB 32
#define HID 2048
#define INNER 4096
#define NH 8
#define HEAD 512
#define K3 12288
#define CAP 30.0f
#define EPS 1e-6f
#define GN_EPS 1e-5f
#define KSCALE 0.044194173824159216f   // 1/sqrt(512)

// ---------------- scratch (device globals; no allocs allowed) ----------------
__device__ float g_xn   [BB * HID];
__device__ float g_xm   [BB * INNER];
__device__ float g_xg   [BB * INNER];
__device__ float g_xmc  [BB * INNER];
__device__ float g_qkv  [BB * K3];
__device__ float g_h    [BB * INNER];
__device__ float g_part [16 * BB * K3];            // split-K partials
__device__ float g_numer[BB * NH * 4 * HEAD];      // cell numer partials
__device__ float g_ig   [BB * NH];
__device__ float g_fg   [BB * NH];

// ---------------- output layout ----------------
#define Y_OFF    0
#define CONV_OFF 65536
#define CELL_OFF 458752
#define NORM_OFF 67567616
#define MAX_OFF  67698688

// ---------------- mma.sync helpers (sm_80 baseline PTX -> HMMA) -------------
__device__ __forceinline__ unsigned pack2(float c0, float c1) {
    // bf16x2 word: low half = bf16(c0), high half = bf16(c1)
    unsigned r;
    asm("cvt.rn.satfinite.bf16x2.f32 %0, %1, %2;" : "=r"(r) : "f"(c1), "f"(c0));
    return r;
}

__device__ __forceinline__ void ldm4(unsigned& r0, unsigned& r1,
                                     unsigned& r2, unsigned& r3, unsigned addr) {
    asm volatile("ldmatrix.sync.aligned.m8n8.x4.shared.b16 {%0,%1,%2,%3}, [%4];"
                 : "=r"(r0), "=r"(r1), "=r"(r2), "=r"(r3) : "r"(addr));
}

__device__ __forceinline__ void mma16816(float* d, const unsigned* a,
                                         unsigned b0, unsigned b1) {
    asm volatile(
        "mma.sync.aligned.m16n8k16.row.col.f32.bf16.bf16.f32 "
        "{%0,%1,%2,%3}, {%4,%5,%6,%7}, {%8,%9}, {%0,%1,%2,%3};"
        : "+f"(d[0]), "+f"(d[1]), "+f"(d[2]), "+f"(d[3])
        : "r"(a[0]), "r"(a[1]), "r"(a[2]), "r"(a[3]), "r"(b0), "r"(b1));
}

// ============================================================================
// MMA GEMM: C[32,N] = A[32,K] @ W[N,K]^T, bf16 hi/lo x3, split-K partials.
// Block: 256 thr, BN=128 W-rows, BK=64. Warp (of 8): 16m x 32n tile.
// Partial layout: [splitIdx][32][nrows]. Dual-W via nb1.
// ============================================================================
#define SW 72   // smem row stride in bf16 elements (144B -> conflict-free)

__global__ __launch_bounds__(256) void mma_gemm(
    const float* __restrict__ A,
    const float* __restrict__ W1, float* __restrict__ P1, int n1,
    const float* __restrict__ W2, float* __restrict__ P2, int n2,
    int nb1, int Kt, int kLen)
{
    __shared__ __align__(16) __nv_bfloat16 sWhi[128 * SW];
    __shared__ __align__(16) __nv_bfloat16 sWlo[128 * SW];
    __shared__ __align__(16) __nv_bfloat16 sAhi[32 * SW];
    __shared__ __align__(16) __nv_bfloat16 sAlo[32 * SW];

    const int t = threadIdx.x;
    const int bx = blockIdx.x;
    const bool fw = bx < nb1;
    const float* W = fw ? W1 : W2;
    float* P = fw ? P1 : P2;
    const int nrows = fw ? n1 : n2;
    const int n0 = (fw ? bx : bx - nb1) * 128;
    const int kBeg = blockIdx.y * kLen;
    const int NCH = kLen >> 6;

    const int wid = t >> 5, l = t & 31;
    const int wm = (wid & 1) * 16;
    const int wn = (wid >> 1) * 32;

    const unsigned swhi = (unsigned)__cvta_generic_to_shared(sWhi);
    const unsigned swlo = (unsigned)__cvta_generic_to_shared(sWlo);
    const unsigned sahi = (unsigned)__cvta_generic_to_shared(sAhi);
    const unsigned salo = (unsigned)__cvta_generic_to_shared(sAlo);

    const float* wbase = W + (size_t)n0 * Kt + kBeg;
    const float* abase = A + kBeg;

    float acc[4][4];
    #pragma unroll
    for (int i = 0; i < 4; i++)
        #pragma unroll
        for (int j = 0; j < 4; j++) acc[i][j] = 0.f;

    for (int ch = 0; ch < NCH; ch++) {
        if (ch) __syncthreads();
        // ---- fill W tile: 128 rows x 64 k ----
        #pragma unroll
        for (int p = 0; p < 8; p++) {
            int id = p * 256 + t;
            int r = id >> 4, c4 = id & 15;
            float4 v = *(const float4*)(wbase + (size_t)r * Kt + ch * 64 + c4 * 4);
            unsigned hi01 = pack2(v.x, v.y);
            unsigned hi23 = pack2(v.z, v.w);
            float h0 = __uint_as_float(hi01 << 16);
            float h1 = __uint_as_float(hi01 & 0xFFFF0000u);
            float h2 = __uint_as_float(hi23 << 16);
            float h3 = __uint_as_float(hi23 & 0xFFFF0000u);
            unsigned lo01 = pack2(v.x - h0, v.y - h1);
            unsigned lo23 = pack2(v.z - h2, v.w - h3);
            int bi = r * SW + c4 * 4;
            *(uint2*)&sWhi[bi] = make_uint2(hi01, hi23);
            *(uint2*)&sWlo[bi] = make_uint2(lo01, lo23);
        }
        // ---- fill A tile: 32 rows x 64 k ----
        #pragma unroll
        for (int p = 0; p < 2; p++) {
            int id = p * 256 + t;
            int r = id >> 4, c4 = id & 15;
            float4 v = *(const float4*)(abase + (size_t)r * Kt + ch * 64 + c4 * 4);
            unsigned hi01 = pack2(v.x, v.y);
            unsigned hi23 = pack2(v.z, v.w);
            float h0 = __uint_as_float(hi01 << 16);
            float h1 = __uint_as_float(hi01 & 0xFFFF0000u);
            float h2 = __uint_as_float(hi23 << 16);
            float h3 = __uint_as_float(hi23 & 0xFFFF0000u);
            unsigned lo01 = pack2(v.x - h0, v.y - h1);
            unsigned lo23 = pack2(v.z - h2, v.w - h3);
            int bi = r * SW + c4 * 4;
            *(uint2*)&sAhi[bi] = make_uint2(hi01, hi23);
            *(uint2*)&sAlo[bi] = make_uint2(lo01, lo23);
        }
        __syncthreads();

        #pragma unroll
        for (int s = 0; s < 4; s++) {
            const int ks = s * 16;
            // A fragments (m16 x k16)
            unsigned arow = wm + ((l >> 3) & 1) * 8 + (l & 7);
            unsigned acol = ks + ((l >> 4) & 1) * 8;
            unsigned aoff = (arow * SW + acol) * 2;
            unsigned ahi[4], alo[4];
            ldm4(ahi[0], ahi[1], ahi[2], ahi[3], sahi + aoff);
            ldm4(alo[0], alo[1], alo[2], alo[3], salo + aoff);
            // B fragments: 4 n8-tiles (k16 x n8 each)
            unsigned brow = wn + ((l >> 4) & 1) * 8 + (l & 7);
            unsigned bcol = ks + ((l >> 3) & 1) * 8;
            unsigned boff0 = (brow * SW + bcol) * 2;
            unsigned boff1 = ((brow + 16) * SW + bcol) * 2;
            unsigned bhi[8], blo[8];
            ldm4(bhi[0], bhi[1], bhi[2], bhi[3], swhi + boff0);
            ldm4(bhi[4], bhi[5], bhi[6], bhi[7], swhi + boff1);
            ldm4(blo[0], blo[1], blo[2], blo[3], swlo + boff0);
            ldm4(blo[4], blo[5], blo[6], blo[7], swlo + boff1);
            #pragma unroll
            for (int tt = 0; tt < 4; tt++) {
                mma16816(acc[tt], ahi, bhi[tt*2], bhi[tt*2+1]);
                mma16816(acc[tt], ahi, blo[tt*2], blo[tt*2+1]);
                mma16816(acc[tt], alo, bhi[tt*2], bhi[tt*2+1]);
            }
        }
    }

    // ---- epilogue: partials [split][b][n] ----
    const int r0 = wm + (l >> 2);
    const int cb = n0 + wn + 2 * (l & 3);
    float* p0 = P + ((size_t)blockIdx.y * 32 + r0) * nrows;
    float* p1 = p0 + (size_t)8 * nrows;
    #pragma unroll
    for (int tt = 0; tt < 4; tt++) {
        *(float2*)(p0 + cb + tt * 8) = make_float2(acc[tt][0], acc[tt][1]);
        *(float2*)(p1 + cb + tt * 8) = make_float2(acc[tt][2], acc[tt][3]);
    }
}

// ============================================================================
// RMSNorm
// ============================================================================
__global__ void rmsnorm_kernel(const float* __restrict__ x,
                               const float* __restrict__ rms_w)
{
    __shared__ float red[256];
    int b = blockIdx.x;
    int tid = threadIdx.x;
    const float* xr = x + b * HID;
    float s = 0.f;
    for (int i = tid; i < HID; i += 256) { float v = xr[i]; s += v * v; }
    red[tid] = s; __syncthreads();
    for (int st = 128; st > 0; st >>= 1) {
        if (tid < st) red[tid] += red[tid + st];
        __syncthreads();
    }
    float rstd = rsqrtf(red[0] / (float)HID + EPS);
    float* o = g_xn + b * HID;
    for (int i = tid; i < HID; i += 256) o[i] = xr[i] * rstd * rms_w[i];
}

// ============================================================================
// Split-K reduce: C = sum_s part[s] (+ addv)
// ============================================================================
template<int S>
__global__ void reduce_split_t(const float* __restrict__ part, int elems,
                               const float* __restrict__ addv,
                               float* __restrict__ C)
{
    int i = blockIdx.x * blockDim.x + threadIdx.x;
    const float4* p = (const float4*)part;
    int q = elems >> 2;
    float4 s = p[i];
    #pragma unroll
    for (int j = 1; j < S; j++) {
        float4 t = p[i + (size_t)j * q];
        s.x += t.x; s.y += t.y; s.z += t.z; s.w += t.w;
    }
    if (addv) {
        float4 a = ((const float4*)addv)[i];
        s.x += a.x; s.y += a.y; s.z += a.z; s.w += a.w;
    }
    ((float4*)C)[i] = s;
}

// ============================================================================
// Conv + silu + new_conv_state
// ============================================================================
__global__ void conv_kernel(const float* __restrict__ conv_state,
                            const float* __restrict__ conv_w,
                            const float* __restrict__ conv_b,
                            float* __restrict__ out)
{
    int idx = blockIdx.x * blockDim.x + threadIdx.x;
    if (idx >= BB * INNER) return;
    int c = idx & (INNER - 1);
    const float* cs = conv_state + (size_t)idx * 3;
    float s0 = cs[0], s1 = cs[1], s2 = cs[2];
    float xm = g_xm[idx];
    const float* w = conv_w + c * 4;
    float xc = s0*w[0] + s1*w[1] + s2*w[2] + xm*w[3] + conv_b[c];
    float* nc = out + CONV_OFF + (size_t)idx * 3;
    nc[0] = s1; nc[1] = s2; nc[2] = xm;
    g_xmc[idx] = xc / (1.f + expf(-xc));
}

// ============================================================================
// Gates
// ============================================================================
__global__ __launch_bounds__(256) void gate_kernel(
    const float* __restrict__ Wi, const float* __restrict__ bi,
    const float* __restrict__ Wf, const float* __restrict__ bf,
    const float* __restrict__ max_state,
    float* __restrict__ out)
{
    __shared__ float ri[256], rf[256];
    int bh = blockIdx.x;
    int h = bh & (NH - 1);
    int b = bh >> 3;
    int tid = threadIdx.x;
    const float4* q4  = (const float4*)(g_qkv + (size_t)b * K3);
    const float4* wi4 = (const float4*)(Wi + (size_t)h * K3);
    const float4* wf4 = (const float4*)(Wf + (size_t)h * K3);
    float si = 0.f, sf = 0.f;
    #pragma unroll
    for (int r = 0; r < K3/4/256; r++) {
        int j = tid + r * 256;
        float4 q = q4[j], a = wi4[j], f = wf4[j];
        si += q.x*a.x + q.y*a.y + q.z*a.z + q.w*a.w;
        sf += q.x*f.x + q.y*f.y + q.z*f.z + q.w*f.w;
    }
    ri[tid] = si; rf[tid] = sf; __syncthreads();
    for (int st = 128; st > 0; st >>= 1) {
        if (tid < st) { ri[tid] += ri[tid+st]; rf[tid] += rf[tid+st]; }
        __syncthreads();
    }
    if (tid == 0) {
        float ig = CAP * tanhf((ri[0] + bi[h]) / CAP);
        float fg = CAP * tanhf((rf[0] + bf[h]) / CAP);
        float lf = (fg >= 0.f) ? -log1pf(expf(-fg)) : (fg - log1pf(expf(fg)));
        float m_old = max_state[bh];
        float m_new = fmaxf(ig, m_old + lf);
        g_ig[bh] = expf(ig - m_new);
        g_fg[bh] = expf(lf + m_old - m_new);
        out[MAX_OFF + bh] = m_new;
    }
}

// ============================================================================
// Cell stream: grid = 4 chunks x 256 bh; 256 threads.
// ============================================================================
__global__ __launch_bounds__(256) void cell_stream(
    const float* __restrict__ cell_state,
    float* __restrict__ out)
{
    __shared__ float qsm[128], ksm[128];
    __shared__ float part[2][HEAD];

    const int bid = blockIdx.x;
    const int bh = bid >> 2;
    const int ch = bid & 3;
    const int h = bh & (NH - 1);
    const int b = bh >> 3;
    const int tid = threadIdx.x;

    const float* qrow = g_qkv + (size_t)b * K3 + h * HEAD;
    const float* krow = qrow + INNER;
    const float* vrow = qrow + 2 * INNER;
    const int d0 = ch * 128;

    if (tid < 128) {
        qsm[tid] = qrow[d0 + tid];
        ksm[tid] = krow[d0 + tid] * KSCALE;
    }
    __syncthreads();

    const float ig = g_ig[bh];
    const float fg = g_fg[bh];

    const int ct = tid & 127;
    const int rg = tid >> 7;
    const int e0 = ct * 4;
    float4 v = *(const float4*)(vrow + e0);
    float4 iv = make_float4(ig*v.x, ig*v.y, ig*v.z, ig*v.w);

    const float* cin  = cell_state + (size_t)bh * HEAD * HEAD;
    float*       cout = out + CELL_OFF + (size_t)bh * HEAD * HEAD;

    float4 nacc = make_float4(0.f, 0.f, 0.f, 0.f);
    #pragma unroll 8
    for (int dd = rg; dd < 128; dd += 2) {
        int d = d0 + dd;
        float4 cv = *(const float4*)(cin + (size_t)d * HEAD + e0);
        float kd = ksm[dd];
        float4 c;
        c.x = fmaf(fg, cv.x, kd * iv.x);
        c.y = fmaf(fg, cv.y, kd * iv.y);
        c.z = fmaf(fg, cv.z, kd * iv.z);
        c.w = fmaf(fg, cv.w, kd * iv.w);
        *(float4*)(cout + (size_t)d * HEAD + e0) = c;
        float qd = qsm[dd];
        nacc.x = fmaf(qd, c.x, nacc.x);
        nacc.y = fmaf(qd, c.y, nacc.y);
        nacc.z = fmaf(qd, c.z, nacc.z);
        nacc.w = fmaf(qd, c.w, nacc.w);
    }
    *(float4*)&part[rg][e0] = nacc;
    __syncthreads();
    if (tid < 128) {
        float4 p0 = *(const float4*)&part[0][e0];
        float4 p1 = *(const float4*)&part[1][e0];
        float4 s = make_float4(p0.x+p1.x, p0.y+p1.y, p0.z+p1.z, p0.w+p1.w);
        *(float4*)(g_numer + (size_t)bid * HEAD + e0) = s;
    }
}

// ============================================================================
// Cell epilogue: norm_new + qn + denom + GroupNorm + gating -> h
// ============================================================================
__global__ __launch_bounds__(512) void cell_epi(
    const float* __restrict__ norm_state,
    const float* __restrict__ gn_w, const float* __restrict__ gn_b,
    const float* __restrict__ skip_w,
    float* __restrict__ out)
{
    __shared__ float red[512];
    const int bh = blockIdx.x;
    const int h = bh & (NH - 1);
    const int b = bh >> 3;
    const int tid = threadIdx.x;

    const float* qrow = g_qkv + (size_t)b * K3 + h * HEAD;
    const float* krow = qrow + INNER;
    float q = qrow[tid];
    float k = krow[tid] * KSCALE;

    const float ig = g_ig[bh];
    const float fg = g_fg[bh];
    const float m_new = out[MAX_OFF + bh];

    float num = g_numer[(size_t)(bh*4+0) * HEAD + tid]
              + g_numer[(size_t)(bh*4+1) * HEAD + tid]
              + g_numer[(size_t)(bh*4+2) * HEAD + tid]
              + g_numer[(size_t)(bh*4+3) * HEAD + tid];

    float nn = fmaf(fg, norm_state[(size_t)bh * HEAD + tid], ig * k);
    out[NORM_OFF + (size_t)bh * HEAD + tid] = nn;

    red[tid] = q * nn; __syncthreads();
    for (int st = 256; st > 0; st >>= 1) {
        if (tid < st) red[tid] += red[tid+st];
        __syncthreads();
    }
    float qn = red[0]; __syncthreads();
    float denom = fmaxf(fabsf(qn), expf(-m_new)) + EPS;
    float o = num / denom;

    red[tid] = o; __syncthreads();
    for (int st = 256; st > 0; st >>= 1) {
        if (tid < st) red[tid] += red[tid+st];
        __syncthreads();
    }
    float mu = red[0] / (float)HEAD; __syncthreads();
    float dv = o - mu;
    red[tid] = dv * dv; __syncthreads();
    for (int st = 256; st > 0; st >>= 1) {
        if (tid < st) red[tid] += red[tid+st];
        __syncthreads();
    }
    float rstd = rsqrtf(red[0] / (float)HEAD + GN_EPS);

    int c = h * HEAD + tid;
    size_t gidx = (size_t)b * INNER + c;
    float og = fmaf(dv * rstd, gn_w[c], gn_b[c]);
    float xg = g_xg[gidx];
    float sg = xg / (1.f + expf(-xg));
    g_h[gidx] = (og + skip_w[c] * g_xmc[gidx]) * sg;
}

// ============================================================================
extern "C" void kernel_launch(void* const* d_in, const int* in_sizes, int n_in,
                              void* d_out, int out_size)
{
    const float* x          = (const float*)d_in[0];
    const float* conv_state = (const float*)d_in[1];
    const float* cell_state = (const float*)d_in[2];
    const float* norm_state = (const float*)d_in[3];
    const float* max_state  = (const float*)d_in[4];
    const float* rms_w      = (const float*)d_in[5];
    const float* Wx         = (const float*)d_in[6];
    const float* Wg         = (const float*)d_in[7];
    const float* Wqkv       = (const float*)d_in[8];
    const float* conv_w     = (const float*)d_in[9];
    const float* conv_b     = (const float*)d_in[10];
    const float* Wi         = (const float*)d_in[11];
    const float* bi         = (const float*)d_in[12];
    const float* Wf         = (const float*)d_in[13];
    const float* bf         = (const float*)d_in[14];
    const float* gn_w       = (const float*)d_in[15];
    const float* gn_b       = (const float*)d_in[16];
    const float* Wdown      = (const float*)d_in[17];
    const float* skip_w     = (const float*)d_in[18];
    float* out = (float*)d_out;

    float* pxn;   cudaGetSymbolAddress((void**)&pxn,   g_xn);
    float* pxm;   cudaGetSymbolAddress((void**)&pxm,   g_xm);
    float* pxg;   cudaGetSymbolAddress((void**)&pxg,   g_xg);
    float* pxmc;  cudaGetSymbolAddress((void**)&pxmc,  g_xmc);
    float* pqkv;  cudaGetSymbolAddress((void**)&pqkv,  g_qkv);
    float* ph;    cudaGetSymbolAddress((void**)&ph,    g_h);
    float* ppart; cudaGetSymbolAddress((void**)&ppart, g_part);

    float* pp2 = ppart + (size_t)2 * BB * INNER;   // Wg partial base

    // 1) rmsnorm
    rmsnorm_kernel<<<BB, 256>>>(x, rms_w);

    // 2) x_mlstm & x_gate tensor-core GEMM, split-K 2: grid (32+32, 2)
    mma_gemm<<<dim3(64, 2), 256>>>(pxn, Wx, ppart, INNER,
                                   Wg, pp2, INNER, 32, HID, HID/2);
    // reduce BEFORE the partial buffer is reused by QKV
    reduce_split_t<2><<<(BB*INNER/4)/256, 256>>>(ppart, BB*INNER, nullptr, pxm);
    reduce_split_t<2><<<(BB*INNER/4)/256, 256>>>(pp2,   BB*INNER, nullptr, pxg);

    // 3) conv + silu + new_conv_state
    conv_kernel<<<(BB*INNER)/256, 256>>>(conv_state, conv_w, conv_b, out);

    // 4) qkv = xmc @ Wqkv^T, split-K 2: grid (96, 2)
    mma_gemm<<<dim3(96, 2), 256>>>(pxmc, Wqkv, ppart, K3,
                                   Wqkv, ppart, K3, 96, INNER, INNER/2);
    reduce_split_t<2><<<(BB*K3/4)/256, 256>>>(ppart, BB*K3, nullptr, pqkv);

    // 5) gates
    gate_kernel<<<BB*NH, 256>>>(Wi, bi, Wf, bf, max_state, out);

    // 6) cell stream: 1024 blocks
    cell_stream<<<BB*NH*4, 256>>>(cell_state, out);

    // 7) cell epilogue -> h
    cell_epi<<<BB*NH, 512>>>(norm_state, gn_w, gn_b, skip_w, out);

    // 8) y = h @ Wdown^T + x, split-K 8: grid (16, 8)
    mma_gemm<<<dim3(16, 8), 256>>>(ph, Wdown, ppart, HID,
                                   Wdown, ppart, HID, 16, INNER, INNER/8);
    reduce_split_t<8><<<(BB*HID/4)/256, 256>>>(ppart, BB*HID, x, out + Y_OFF);
}

// round 10
// speedup vs baseline: 1.5096x; 1.3231x over previous
#include <cuda_runtime.h>
#include <cuda_bf16.h>
#include <math.h>
#include <stdint.h>

#define BB 32
#define HID 2048
#define INNER 4096
#define NH 8
#define HEAD 512
#define K3 12288
#define CAP 30.0f
#define EPS 1e-6f
#define GN_EPS 1e-5f
#define KSCALE 0.044194173824159216f   // 1/sqrt(512)

// ---------------- scratch (device globals; no allocs allowed) ----------------
__device__ float g_xn   [BB * HID];
__device__ float g_xm   [BB * INNER];
__device__ float g_xg   [BB * INNER];
__device__ float g_xmc  [BB * INNER];
__device__ float g_qkv  [BB * K3];
__device__ float g_h    [BB * INNER];
__device__ float g_part [16 * BB * K3];            // split-K partials
__device__ float g_numer[BB * NH * 4 * HEAD];      // cell numer partials
__device__ float g_ig   [BB * NH];
__device__ float g_fg   [BB * NH];

// ---------------- output layout ----------------
#define Y_OFF    0
#define CONV_OFF 65536
#define CELL_OFF 458752
#define NORM_OFF 67567616
#define MAX_OFF  67698688

// ---------------- mma.sync helpers (sm_80 baseline PTX -> HMMA) -------------
__device__ __forceinline__ unsigned pack2(float c0, float c1) {
    unsigned r;
    asm("cvt.rn.satfinite.bf16x2.f32 %0, %1, %2;" : "=r"(r) : "f"(c1), "f"(c0));
    return r;
}

__device__ __forceinline__ void ldm4(unsigned& r0, unsigned& r1,
                                     unsigned& r2, unsigned& r3, unsigned addr) {
    asm volatile("ldmatrix.sync.aligned.m8n8.x4.shared.b16 {%0,%1,%2,%3}, [%4];"
                 : "=r"(r0), "=r"(r1), "=r"(r2), "=r"(r3) : "r"(addr));
}

__device__ __forceinline__ void mma16816(float* d, const unsigned* a,
                                         unsigned b0, unsigned b1) {
    asm volatile(
        "mma.sync.aligned.m16n8k16.row.col.f32.bf16.bf16.f32 "
        "{%0,%1,%2,%3}, {%4,%5,%6,%7}, {%8,%9}, {%0,%1,%2,%3};"
        : "+f"(d[0]), "+f"(d[1]), "+f"(d[2]), "+f"(d[3])
        : "r"(a[0]), "r"(a[1]), "r"(a[2]), "r"(a[3]), "r"(b0), "r"(b1));
}

// convert one float4 to hi/lo bf16x2 pairs
__device__ __forceinline__ void cvt_hilo(float4 v, uint2& hi, uint2& lo) {
    unsigned hi01 = pack2(v.x, v.y);
    unsigned hi23 = pack2(v.z, v.w);
    float h0 = __uint_as_float(hi01 << 16);
    float h1 = __uint_as_float(hi01 & 0xFFFF0000u);
    float h2 = __uint_as_float(hi23 << 16);
    float h3 = __uint_as_float(hi23 & 0xFFFF0000u);
    hi = make_uint2(hi01, hi23);
    lo = make_uint2(pack2(v.x - h0, v.y - h1), pack2(v.z - h2, v.w - h3));
}

// ============================================================================
// MMA GEMM: C[32,N] = A[32,K] @ W[N,K]^T, bf16 hi/lo x3, split-K partials.
// Block: 256 thr, BN=128 W-rows, BK=32, register-prefetch pipelining.
// Warp (of 8): 16m x 32n tile. Partial layout: [splitIdx][32][nrows].
// ============================================================================
#define SW 40   // smem row stride in bf16 elems (80B) - ldmatrix conflict-free

__global__ __launch_bounds__(256) void mma_gemm(
    const float* __restrict__ A,
    const float* __restrict__ W1, float* __restrict__ P1, int n1,
    const float* __restrict__ W2, float* __restrict__ P2, int n2,
    int nb1, int Kt, int kLen)
{
    __shared__ __align__(16) __nv_bfloat16 sWhi[128 * SW];
    __shared__ __align__(16) __nv_bfloat16 sWlo[128 * SW];
    __shared__ __align__(16) __nv_bfloat16 sAhi[32 * SW];
    __shared__ __align__(16) __nv_bfloat16 sAlo[32 * SW];

    const int t = threadIdx.x;
    const int bx = blockIdx.x;
    const bool fw = bx < nb1;
    const float* W = fw ? W1 : W2;
    float* P = fw ? P1 : P2;
    const int nrows = fw ? n1 : n2;
    const int n0 = (fw ? bx : bx - nb1) * 128;
    const int kBeg = blockIdx.y * kLen;
    const int NCH = kLen >> 5;

    const int wid = t >> 5, l = t & 31;
    const int wm = (wid & 1) * 16;
    const int wn = (wid >> 1) * 32;

    const unsigned swhi = (unsigned)__cvta_generic_to_shared(sWhi);
    const unsigned swlo = (unsigned)__cvta_generic_to_shared(sWlo);
    const unsigned sahi = (unsigned)__cvta_generic_to_shared(sAhi);
    const unsigned salo = (unsigned)__cvta_generic_to_shared(sAlo);

    const int lr = t >> 3;        // 0..31  (row within 32-row group)
    const int lc = t & 7;         // float4 column
    const float* wsrc = W + (size_t)(n0 + lr) * Kt + kBeg + lc * 4;
    const float* asrc = A + (size_t)lr * Kt + kBeg + lc * 4;
    const int sbi = lr * SW + lc * 4;   // smem elem index base (rows +32 per p)

    float acc[4][4];
    #pragma unroll
    for (int i = 0; i < 4; i++)
        #pragma unroll
        for (int j = 0; j < 4; j++) acc[i][j] = 0.f;

    // prefetch chunk 0
    float4 wpre[4], apre;
    #pragma unroll
    for (int p = 0; p < 4; p++)
        wpre[p] = *(const float4*)(wsrc + (size_t)(p * 32) * Kt);
    apre = *(const float4*)asrc;

    for (int ch = 0; ch < NCH; ch++) {
        if (ch) __syncthreads();
        // convert regs -> smem
        #pragma unroll
        for (int p = 0; p < 4; p++) {
            uint2 hi, lo; cvt_hilo(wpre[p], hi, lo);
            *(uint2*)&sWhi[p * 32 * SW + sbi] = hi;
            *(uint2*)&sWlo[p * 32 * SW + sbi] = lo;
        }
        {
            uint2 hi, lo; cvt_hilo(apre, hi, lo);
            *(uint2*)&sAhi[sbi] = hi;
            *(uint2*)&sAlo[sbi] = lo;
        }
        __syncthreads();
        // issue next chunk's loads (latency hides under compute)
        if (ch + 1 < NCH) {
            #pragma unroll
            for (int p = 0; p < 4; p++)
                wpre[p] = *(const float4*)(wsrc + (size_t)(p * 32) * Kt + (ch + 1) * 32);
            apre = *(const float4*)(asrc + (ch + 1) * 32);
        }
        // compute: 2 k16 steps
        #pragma unroll
        for (int s = 0; s < 2; s++) {
            const int ks = s * 16;
            unsigned arow = wm + ((l >> 3) & 1) * 8 + (l & 7);
            unsigned acol = ks + ((l >> 4) & 1) * 8;
            unsigned aoff = (arow * SW + acol) * 2;
            unsigned ahi[4], alo[4];
            ldm4(ahi[0], ahi[1], ahi[2], ahi[3], sahi + aoff);
            ldm4(alo[0], alo[1], alo[2], alo[3], salo + aoff);
            unsigned brow = wn + ((l >> 4) & 1) * 8 + (l & 7);
            unsigned bcol = ks + ((l >> 3) & 1) * 8;
            unsigned boff0 = (brow * SW + bcol) * 2;
            unsigned boff1 = ((brow + 16) * SW + bcol) * 2;
            unsigned bhi[8], blo[8];
            ldm4(bhi[0], bhi[1], bhi[2], bhi[3], swhi + boff0);
            ldm4(bhi[4], bhi[5], bhi[6], bhi[7], swhi + boff1);
            ldm4(blo[0], blo[1], blo[2], blo[3], swlo + boff0);
            ldm4(blo[4], blo[5], blo[6], blo[7], swlo + boff1);
            #pragma unroll
            for (int tt = 0; tt < 4; tt++) {
                mma16816(acc[tt], ahi, bhi[tt*2], bhi[tt*2+1]);
                mma16816(acc[tt], ahi, blo[tt*2], blo[tt*2+1]);
                mma16816(acc[tt], alo, bhi[tt*2], bhi[tt*2+1]);
            }
        }
    }

    // ---- epilogue: partials [split][b][n] ----
    const int r0 = wm + (l >> 2);
    const int cb = n0 + wn + 2 * (l & 3);
    float* p0 = P + ((size_t)blockIdx.y * 32 + r0) * nrows;
    float* p1 = p0 + (size_t)8 * nrows;
    #pragma unroll
    for (int tt = 0; tt < 4; tt++) {
        *(float2*)(p0 + cb + tt * 8) = make_float2(acc[tt][0], acc[tt][1]);
        *(float2*)(p1 + cb + tt * 8) = make_float2(acc[tt][2], acc[tt][3]);
    }
}

// ============================================================================
// RMSNorm
// ============================================================================
__global__ void rmsnorm_kernel(const float* __restrict__ x,
                               const float* __restrict__ rms_w)
{
    __shared__ float red[256];
    int b = blockIdx.x;
    int tid = threadIdx.x;
    const float* xr = x + b * HID;
    float s = 0.f;
    for (int i = tid; i < HID; i += 256) { float v = xr[i]; s += v * v; }
    red[tid] = s; __syncthreads();
    for (int st = 128; st > 0; st >>= 1) {
        if (tid < st) red[tid] += red[tid + st];
        __syncthreads();
    }
    float rstd = rsqrtf(red[0] / (float)HID + EPS);
    float* o = g_xn + b * HID;
    for (int i = tid; i < HID; i += 256) o[i] = xr[i] * rstd * rms_w[i];
}

// ============================================================================
// Split-K reduce: C = sum_s part[s] (+ addv)
// ============================================================================
template<int S>
__global__ void reduce_split_t(const float* __restrict__ part, int elems,
                               const float* __restrict__ addv,
                               float* __restrict__ C)
{
    int i = blockIdx.x * blockDim.x + threadIdx.x;
    const float4* p = (const float4*)part;
    int q = elems >> 2;
    float4 s = p[i];
    #pragma unroll
    for (int j = 1; j < S; j++) {
        float4 t = p[i + (size_t)j * q];
        s.x += t.x; s.y += t.y; s.z += t.z; s.w += t.w;
    }
    if (addv) {
        float4 a = ((const float4*)addv)[i];
        s.x += a.x; s.y += a.y; s.z += a.z; s.w += a.w;
    }
    ((float4*)C)[i] = s;
}

// ============================================================================
// Conv + silu + new_conv_state
// ============================================================================
__global__ void conv_kernel(const float* __restrict__ conv_state,
                            const float* __restrict__ conv_w,
                            const float* __restrict__ conv_b,
                            float* __restrict__ out)
{
    int idx = blockIdx.x * blockDim.x + threadIdx.x;
    if (idx >= BB * INNER) return;
    int c = idx & (INNER - 1);
    const float* cs = conv_state + (size_t)idx * 3;
    float s0 = cs[0], s1 = cs[1], s2 = cs[2];
    float xm = g_xm[idx];
    const float* w = conv_w + c * 4;
    float xc = s0*w[0] + s1*w[1] + s2*w[2] + xm*w[3] + conv_b[c];
    float* nc = out + CONV_OFF + (size_t)idx * 3;
    nc[0] = s1; nc[1] = s2; nc[2] = xm;
    g_xmc[idx] = xc / (1.f + expf(-xc));
}

// ============================================================================
// Gates
// ============================================================================
__global__ __launch_bounds__(256) void gate_kernel(
    const float* __restrict__ Wi, const float* __restrict__ bi,
    const float* __restrict__ Wf, const float* __restrict__ bf,
    const float* __restrict__ max_state,
    float* __restrict__ out)
{
    __shared__ float ri[256], rf[256];
    int bh = blockIdx.x;
    int h = bh & (NH - 1);
    int b = bh >> 3;
    int tid = threadIdx.x;
    const float4* q4  = (const float4*)(g_qkv + (size_t)b * K3);
    const float4* wi4 = (const float4*)(Wi + (size_t)h * K3);
    const float4* wf4 = (const float4*)(Wf + (size_t)h * K3);
    float si = 0.f, sf = 0.f;
    #pragma unroll
    for (int r = 0; r < K3/4/256; r++) {
        int j = tid + r * 256;
        float4 q = q4[j], a = wi4[j], f = wf4[j];
        si += q.x*a.x + q.y*a.y + q.z*a.z + q.w*a.w;
        sf += q.x*f.x + q.y*f.y + q.z*f.z + q.w*f.w;
    }
    ri[tid] = si; rf[tid] = sf; __syncthreads();
    for (int st = 128; st > 0; st >>= 1) {
        if (tid < st) { ri[tid] += ri[tid+st]; rf[tid] += rf[tid+st]; }
        __syncthreads();
    }
    if (tid == 0) {
        float ig = CAP * tanhf((ri[0] + bi[h]) / CAP);
        float fg = CAP * tanhf((rf[0] + bf[h]) / CAP);
        float lf = (fg >= 0.f) ? -log1pf(expf(-fg)) : (fg - log1pf(expf(fg)));
        float m_old = max_state[bh];
        float m_new = fmaxf(ig, m_old + lf);
        g_ig[bh] = expf(ig - m_new);
        g_fg[bh] = expf(lf + m_old - m_new);
        out[MAX_OFF + bh] = m_new;
    }
}

// ============================================================================
// Cell stream: grid = 4 chunks x 256 bh; 256 threads.
// ============================================================================
__global__ __launch_bounds__(256) void cell_stream(
    const float* __restrict__ cell_state,
    float* __restrict__ out)
{
    __shared__ float qsm[128], ksm[128];
    __shared__ float part[2][HEAD];

    const int bid = blockIdx.x;
    const int bh = bid >> 2;
    const int ch = bid & 3;
    const int h = bh & (NH - 1);
    const int b = bh >> 3;
    const int tid = threadIdx.x;

    const float* qrow = g_qkv + (size_t)b * K3 + h * HEAD;
    const float* krow = qrow + INNER;
    const float* vrow = qrow + 2 * INNER;
    const int d0 = ch * 128;

    if (tid < 128) {
        qsm[tid] = qrow[d0 + tid];
        ksm[tid] = krow[d0 + tid] * KSCALE;
    }
    __syncthreads();

    const float ig = g_ig[bh];
    const float fg = g_fg[bh];

    const int ct = tid & 127;
    const int rg = tid >> 7;
    const int e0 = ct * 4;
    float4 v = *(const float4*)(vrow + e0);
    float4 iv = make_float4(ig*v.x, ig*v.y, ig*v.z, ig*v.w);

    const float* cin  = cell_state + (size_t)bh * HEAD * HEAD;
    float*       cout = out + CELL_OFF + (size_t)bh * HEAD * HEAD;

    float4 nacc = make_float4(0.f, 0.f, 0.f, 0.f);
    #pragma unroll 8
    for (int dd = rg; dd < 128; dd += 2) {
        int d = d0 + dd;
        float4 cv = *(const float4*)(cin + (size_t)d * HEAD + e0);
        float kd = ksm[dd];
        float4 c;
        c.x = fmaf(fg, cv.x, kd * iv.x);
        c.y = fmaf(fg, cv.y, kd * iv.y);
        c.z = fmaf(fg, cv.z, kd * iv.z);
        c.w = fmaf(fg, cv.w, kd * iv.w);
        *(float4*)(cout + (size_t)d * HEAD + e0) = c;
        float qd = qsm[dd];
        nacc.x = fmaf(qd, c.x, nacc.x);
        nacc.y = fmaf(qd, c.y, nacc.y);
        nacc.z = fmaf(qd, c.z, nacc.z);
        nacc.w = fmaf(qd, c.w, nacc.w);
    }
    *(float4*)&part[rg][e0] = nacc;
    __syncthreads();
    if (tid < 128) {
        float4 p0 = *(const float4*)&part[0][e0];
        float4 p1 = *(const float4*)&part[1][e0];
        float4 s = make_float4(p0.x+p1.x, p0.y+p1.y, p0.z+p1.z, p0.w+p1.w);
        *(float4*)(g_numer + (size_t)bid * HEAD + e0) = s;
    }
}

// ============================================================================
// Cell epilogue: norm_new + qn + denom + GroupNorm + gating -> h
// ============================================================================
__global__ __launch_bounds__(512) void cell_epi(
    const float* __restrict__ norm_state,
    const float* __restrict__ gn_w, const float* __restrict__ gn_b,
    const float* __restrict__ skip_w,
    float* __restrict__ out)
{
    __shared__ float red[512];
    const int bh = blockIdx.x;
    const int h = bh & (NH - 1);
    const int b = bh >> 3;
    const int tid = threadIdx.x;

    const float* qrow = g_qkv + (size_t)b * K3 + h * HEAD;
    const float* krow = qrow + INNER;
    float q = qrow[tid];
    float k = krow[tid] * KSCALE;

    const float ig = g_ig[bh];
    const float fg = g_fg[bh];
    const float m_new = out[MAX_OFF + bh];

    float num = g_numer[(size_t)(bh*4+0) * HEAD + tid]
              + g_numer[(size_t)(bh*4+1) * HEAD + tid]
              + g_numer[(size_t)(bh*4+2) * HEAD + tid]
              + g_numer[(size_t)(bh*4+3) * HEAD + tid];

    float nn = fmaf(fg, norm_state[(size_t)bh * HEAD + tid], ig * k);
    out[NORM_OFF + (size_t)bh * HEAD + tid] = nn;

    red[tid] = q * nn; __syncthreads();
    for (int st = 256; st > 0; st >>= 1) {
        if (tid < st) red[tid] += red[tid+st];
        __syncthreads();
    }
    float qn = red[0]; __syncthreads();
    float denom = fmaxf(fabsf(qn), expf(-m_new)) + EPS;
    float o = num / denom;

    red[tid] = o; __syncthreads();
    for (int st = 256; st > 0; st >>= 1) {
        if (tid < st) red[tid] += red[tid+st];
        __syncthreads();
    }
    float mu = red[0] / (float)HEAD; __syncthreads();
    float dv = o - mu;
    red[tid] = dv * dv; __syncthreads();
    for (int st = 256; st > 0; st >>= 1) {
        if (tid < st) red[tid] += red[tid+st];
        __syncthreads();
    }
    float rstd = rsqrtf(red[0] / (float)HEAD + GN_EPS);

    int c = h * HEAD + tid;
    size_t gidx = (size_t)b * INNER + c;
    float og = fmaf(dv * rstd, gn_w[c], gn_b[c]);
    float xg = g_xg[gidx];
    float sg = xg / (1.f + expf(-xg));
    g_h[gidx] = (og + skip_w[c] * g_xmc[gidx]) * sg;
}

// ============================================================================
extern "C" void kernel_launch(void* const* d_in, const int* in_sizes, int n_in,
                              void* d_out, int out_size)
{
    const float* x          = (const float*)d_in[0];
    const float* conv_state = (const float*)d_in[1];
    const float* cell_state = (const float*)d_in[2];
    const float* norm_state = (const float*)d_in[3];
    const float* max_state  = (const float*)d_in[4];
    const float* rms_w      = (const float*)d_in[5];
    const float* Wx         = (const float*)d_in[6];
    const float* Wg         = (const float*)d_in[7];
    const float* Wqkv       = (const float*)d_in[8];
    const float* conv_w     = (const float*)d_in[9];
    const float* conv_b     = (const float*)d_in[10];
    const float* Wi         = (const float*)d_in[11];
    const float* bi         = (const float*)d_in[12];
    const float* Wf         = (const float*)d_in[13];
    const float* bf         = (const float*)d_in[14];
    const float* gn_w       = (const float*)d_in[15];
    const float* gn_b       = (const float*)d_in[16];
    const float* Wdown      = (const float*)d_in[17];
    const float* skip_w     = (const float*)d_in[18];
    float* out = (float*)d_out;

    float* pxn;   cudaGetSymbolAddress((void**)&pxn,   g_xn);
    float* pxm;   cudaGetSymbolAddress((void**)&pxm,   g_xm);
    float* pxg;   cudaGetSymbolAddress((void**)&pxg,   g_xg);
    float* pxmc;  cudaGetSymbolAddress((void**)&pxmc,  g_xmc);
    float* pqkv;  cudaGetSymbolAddress((void**)&pqkv,  g_qkv);
    float* ph;    cudaGetSymbolAddress((void**)&ph,    g_h);
    float* ppart; cudaGetSymbolAddress((void**)&ppart, g_part);

    float* pp2 = ppart + (size_t)2 * BB * INNER;   // Wg partial base

    // 1) rmsnorm
    rmsnorm_kernel<<<BB, 256>>>(x, rms_w);

    // 2) x_mlstm & x_gate tensor-core GEMM, split-K 2: grid (32+32, 2)
    mma_gemm<<<dim3(64, 2), 256>>>(pxn, Wx, ppart, INNER,
                                   Wg, pp2, INNER, 32, HID, HID/2);
    // reduce BEFORE the partial buffer is reused by QKV
    reduce_split_t<2><<<(BB*INNER/4)/256, 256>>>(ppart, BB*INNER, nullptr, pxm);
    reduce_split_t<2><<<(BB*INNER/4)/256, 256>>>(pp2,   BB*INNER, nullptr, pxg);

    // 3) conv + silu + new_conv_state
    conv_kernel<<<(BB*INNER)/256, 256>>>(conv_state, conv_w, conv_b, out);

    // 4) qkv = xmc @ Wqkv^T, split-K 2: grid (96, 2)
    mma_gemm<<<dim3(96, 2), 256>>>(pxmc, Wqkv, ppart, K3,
                                   Wqkv, ppart, K3, 96, INNER, INNER/2);
    reduce_split_t<2><<<(BB*K3/4)/256, 256>>>(ppart, BB*K3, nullptr, pqkv);

    // 5) gates
    gate_kernel<<<BB*NH, 256>>>(Wi, bi, Wf, bf, max_state, out);

    // 6) cell stream: 1024 blocks
    cell_stream<<<BB*NH*4, 256>>>(cell_state, out);

    // 7) cell epilogue -> h
    cell_epi<<<BB*NH, 512>>>(norm_state, gn_w, gn_b, skip_w, out);

    // 8) y = h @ Wdown^T + x, split-K 8: grid (16, 8)
    mma_gemm<<<dim3(16, 8), 256>>>(ph, Wdown, ppart, HID,
                                   Wdown, ppart, HID, 16, INNER, INNER/8);
    reduce_split_t<8><<<(BB*HID/4)/256, 256>>>(ppart, BB*HID, x, out + Y_OFF);
}

// round 11
// speedup vs baseline: 1.8067x; 1.1968x over previous
#include <cuda_runtime.h>
#include <cuda_bf16.h>
#include <math.h>
#include <stdint.h>

#define BB 32
#define HID 2048
#define INNER 4096
#define NH 8
#define HEAD 512
#define K3 12288
#define CAP 30.0f
#define EPS 1e-6f
#define GN_EPS 1e-5f
#define KSCALE 0.044194173824159216f   // 1/sqrt(512)

// ---------------- scratch (device globals; no allocs allowed) ----------------
__device__ float g_xn   [BB * HID];
__device__ float g_xg   [BB * INNER];
__device__ float g_xmc  [BB * INNER];
__device__ float g_qkv  [BB * K3];
__device__ float g_h    [BB * INNER];
__device__ float g_part [16 * BB * K3];            // split-K partials
__device__ float g_numer[BB * NH * 4 * HEAD];      // cell numer partials
__device__ float g_ig   [BB * NH];
__device__ float g_fg   [BB * NH];

// ---------------- output layout ----------------
#define Y_OFF    0
#define CONV_OFF 65536
#define CELL_OFF 458752
#define NORM_OFF 67567616
#define MAX_OFF  67698688

// ---------------- mma.sync helpers (sm_80 baseline PTX -> HMMA) -------------
__device__ __forceinline__ unsigned pack2(float c0, float c1) {
    unsigned r;
    asm("cvt.rn.satfinite.bf16x2.f32 %0, %1, %2;" : "=r"(r) : "f"(c1), "f"(c0));
    return r;
}

__device__ __forceinline__ void ldm4(unsigned& r0, unsigned& r1,
                                     unsigned& r2, unsigned& r3, unsigned addr) {
    asm volatile("ldmatrix.sync.aligned.m8n8.x4.shared.b16 {%0,%1,%2,%3}, [%4];"
                 : "=r"(r0), "=r"(r1), "=r"(r2), "=r"(r3) : "r"(addr));
}

__device__ __forceinline__ void mma16816(float* d, const unsigned* a,
                                         unsigned b0, unsigned b1) {
    asm volatile(
        "mma.sync.aligned.m16n8k16.row.col.f32.bf16.bf16.f32 "
        "{%0,%1,%2,%3}, {%4,%5,%6,%7}, {%8,%9}, {%0,%1,%2,%3};"
        : "+f"(d[0]), "+f"(d[1]), "+f"(d[2]), "+f"(d[3])
        : "r"(a[0]), "r"(a[1]), "r"(a[2]), "r"(a[3]), "r"(b0), "r"(b1));
}

__device__ __forceinline__ void cvt_hilo(float4 v, uint2& hi, uint2& lo) {
    unsigned hi01 = pack2(v.x, v.y);
    unsigned hi23 = pack2(v.z, v.w);
    float h0 = __uint_as_float(hi01 << 16);
    float h1 = __uint_as_float(hi01 & 0xFFFF0000u);
    float h2 = __uint_as_float(hi23 << 16);
    float h3 = __uint_as_float(hi23 & 0xFFFF0000u);
    hi = make_uint2(hi01, hi23);
    lo = make_uint2(pack2(v.x - h0, v.y - h1), pack2(v.z - h2, v.w - h3));
}

__device__ __forceinline__ void cp16(void* smem_p, const void* g) {
    unsigned s = (unsigned)__cvta_generic_to_shared(smem_p);
    asm volatile("cp.async.cg.shared.global [%0], [%1], 16;\n" :: "r"(s), "l"(g));
}

// ============================================================================
// MMA GEMM v3: C[32,N] = A[32,K] @ W[N,K]^T, bf16 hi/lo x3, split-K partials.
// 256 thr, BN=128, BK=32. cp.async 2-deep fp32 staging -> convert -> bf16 smem.
// Warp (of 8): 16m x 32n tile. Partial layout: [splitIdx][32][nrows].
// ============================================================================
#define SW 40   // bf16 smem row stride (80B) - ldmatrix conflict-free
// dynamic smem offsets (bytes)
#define O_WST 0               // fp32 W stage: 2 * 128*32*4 = 32768
#define O_AST 32768           // fp32 A stage: 2 * 32*32*4  = 8192
#define O_WHI 40960           // 128*SW*2 = 10240
#define O_WLO 51200
#define O_AHI 61440           // 32*SW*2 = 2560
#define O_ALO 64000
#define SMEM_MMA 66560

__global__ __launch_bounds__(256) void mma_gemm(
    const float* __restrict__ A,
    const float* __restrict__ W1, float* __restrict__ P1, int n1,
    const float* __restrict__ W2, float* __restrict__ P2, int n2,
    int nb1, int Kt, int kLen)
{
    extern __shared__ __align__(16) char smem[];
    float* stW = (float*)(smem + O_WST);
    float* stA = (float*)(smem + O_AST);
    __nv_bfloat16* sWhi = (__nv_bfloat16*)(smem + O_WHI);
    __nv_bfloat16* sWlo = (__nv_bfloat16*)(smem + O_WLO);
    __nv_bfloat16* sAhi = (__nv_bfloat16*)(smem + O_AHI);
    __nv_bfloat16* sAlo = (__nv_bfloat16*)(smem + O_ALO);
    const unsigned sbase = (unsigned)__cvta_generic_to_shared(smem);
    const unsigned swhi = sbase + O_WHI;
    const unsigned swlo = sbase + O_WLO;
    const unsigned sahi = sbase + O_AHI;
    const unsigned salo = sbase + O_ALO;

    const int t = threadIdx.x;
    const int bx = blockIdx.x;
    const bool fw = bx < nb1;
    const float* W = fw ? W1 : W2;
    float* P = fw ? P1 : P2;
    const int nrows = fw ? n1 : n2;
    const int n0 = (fw ? bx : bx - nb1) * 128;
    const int kBeg = blockIdx.y * kLen;
    const int NCH = kLen >> 5;

    const int wid = t >> 5, l = t & 31;
    const int wm = (wid & 1) * 16;
    const int wn = (wid >> 1) * 32;

    const int lr = t >> 3;        // 0..31
    const int lc = t & 7;         // float4 col
    const float* wsrc = W + (size_t)(n0 + lr) * Kt + kBeg + lc * 4;
    const float* asrc = A + (size_t)lr * Kt + kBeg + lc * 4;
    const int wsl = lr * 32 + lc * 4;   // stage slot (per 32-row group)
    const int asl = lr * 32 + lc * 4;

    float acc[4][4];
    #pragma unroll
    for (int i = 0; i < 4; i++)
        #pragma unroll
        for (int j = 0; j < 4; j++) acc[i][j] = 0.f;

    // prologue: stage chunks 0,1
    {
        #pragma unroll
        for (int p = 0; p < 4; p++)
            cp16(&stW[p * 1024 + wsl], wsrc + (size_t)(p * 32) * Kt);
        cp16(&stA[asl], asrc);
        asm volatile("cp.async.commit_group;\n");
        if (NCH > 1) {
            #pragma unroll
            for (int p = 0; p < 4; p++)
                cp16(&stW[4096 + p * 1024 + wsl], wsrc + (size_t)(p * 32) * Kt + 32);
            cp16(&stA[1024 + asl], asrc + 32);
            asm volatile("cp.async.commit_group;\n");
        }
    }

    for (int ch = 0; ch < NCH; ch++) {
        const int st = ch & 1;
        if (ch + 1 < NCH) asm volatile("cp.async.wait_group 1;\n");
        else              asm volatile("cp.async.wait_group 0;\n");
        __syncthreads();   // stage ready + prev compute done reading bf16

        // convert fp32 stage -> bf16 hi/lo smem
        #pragma unroll
        for (int p = 0; p < 4; p++) {
            float4 v = *(const float4*)&stW[st * 4096 + p * 1024 + wsl];
            uint2 hi, lo; cvt_hilo(v, hi, lo);
            int bi = (lr + 32 * p) * SW + lc * 4;
            *(uint2*)&sWhi[bi] = hi;
            *(uint2*)&sWlo[bi] = lo;
        }
        {
            float4 v = *(const float4*)&stA[st * 1024 + asl];
            uint2 hi, lo; cvt_hilo(v, hi, lo);
            int bi = lr * SW + lc * 4;
            *(uint2*)&sAhi[bi] = hi;
            *(uint2*)&sAlo[bi] = lo;
        }
        __syncthreads();   // bf16 visible; stage reads complete

        // refill stage st with chunk ch+2
        if (ch + 2 < NCH) {
            #pragma unroll
            for (int p = 0; p < 4; p++)
                cp16(&stW[st * 4096 + p * 1024 + wsl],
                     wsrc + (size_t)(p * 32) * Kt + (ch + 2) * 32);
            cp16(&stA[st * 1024 + asl], asrc + (ch + 2) * 32);
            asm volatile("cp.async.commit_group;\n");
        }

        // compute: 2 k16 steps
        #pragma unroll
        for (int s = 0; s < 2; s++) {
            const int ks = s * 16;
            unsigned arow = wm + ((l >> 3) & 1) * 8 + (l & 7);
            unsigned acol = ks + ((l >> 4) & 1) * 8;
            unsigned aoff = (arow * SW + acol) * 2;
            unsigned ahi[4], alo[4];
            ldm4(ahi[0], ahi[1], ahi[2], ahi[3], sahi + aoff);
            ldm4(alo[0], alo[1], alo[2], alo[3], salo + aoff);
            unsigned brow = wn + ((l >> 4) & 1) * 8 + (l & 7);
            unsigned bcol = ks + ((l >> 3) & 1) * 8;
            unsigned boff0 = (brow * SW + bcol) * 2;
            unsigned boff1 = ((brow + 16) * SW + bcol) * 2;
            unsigned bhi[8], blo[8];
            ldm4(bhi[0], bhi[1], bhi[2], bhi[3], swhi + boff0);
            ldm4(bhi[4], bhi[5], bhi[6], bhi[7], swhi + boff1);
            ldm4(blo[0], blo[1], blo[2], blo[3], swlo + boff0);
            ldm4(blo[4], blo[5], blo[6], blo[7], swlo + boff1);
            #pragma unroll
            for (int tt = 0; tt < 4; tt++) {
                mma16816(acc[tt], ahi, bhi[tt*2], bhi[tt*2+1]);
                mma16816(acc[tt], ahi, blo[tt*2], blo[tt*2+1]);
                mma16816(acc[tt], alo, bhi[tt*2], bhi[tt*2+1]);
            }
        }
    }

    // ---- epilogue: partials [split][b][n] ----
    const int r0 = wm + (l >> 2);
    const int cb = n0 + wn + 2 * (l & 3);
    float* p0 = P + ((size_t)blockIdx.y * 32 + r0) * nrows;
    float* p1 = p0 + (size_t)8 * nrows;
    #pragma unroll
    for (int tt = 0; tt < 4; tt++) {
        *(float2*)(p0 + cb + tt * 8) = make_float2(acc[tt][0], acc[tt][1]);
        *(float2*)(p1 + cb + tt * 8) = make_float2(acc[tt][2], acc[tt][3]);
    }
}

// ============================================================================
// RMSNorm
// ============================================================================
__global__ void rmsnorm_kernel(const float* __restrict__ x,
                               const float* __restrict__ rms_w)
{
    __shared__ float red[256];
    int b = blockIdx.x;
    int tid = threadIdx.x;
    const float* xr = x + b * HID;
    float s = 0.f;
    for (int i = tid; i < HID; i += 256) { float v = xr[i]; s += v * v; }
    red[tid] = s; __syncthreads();
    for (int st = 128; st > 0; st >>= 1) {
        if (tid < st) red[tid] += red[tid + st];
        __syncthreads();
    }
    float rstd = rsqrtf(red[0] / (float)HID + EPS);
    float* o = g_xn + b * HID;
    for (int i = tid; i < HID; i += 256) o[i] = xr[i] * rstd * rms_w[i];
}

// ============================================================================
// Split-K reduce: C = sum_s part[s] (+ addv)
// ============================================================================
template<int S>
__global__ void reduce_split_t(const float* __restrict__ part, int elems,
                               const float* __restrict__ addv,
                               float* __restrict__ C)
{
    int i = blockIdx.x * blockDim.x + threadIdx.x;
    const float4* p = (const float4*)part;
    int q = elems >> 2;
    float4 s = p[i];
    #pragma unroll
    for (int j = 1; j < S; j++) {
        float4 t = p[i + (size_t)j * q];
        s.x += t.x; s.y += t.y; s.z += t.z; s.w += t.w;
    }
    if (addv) {
        float4 a = ((const float4*)addv)[i];
        s.x += a.x; s.y += a.y; s.z += a.z; s.w += a.w;
    }
    ((float4*)C)[i] = s;
}

// ============================================================================
// Conv + fused xm split-4 reduce + silu + new_conv_state
// ============================================================================
__global__ void conv_kernel(const float* __restrict__ conv_state,
                            const float* __restrict__ conv_w,
                            const float* __restrict__ conv_b,
                            const float* __restrict__ xm_part,
                            float* __restrict__ out)
{
    int idx = blockIdx.x * blockDim.x + threadIdx.x;
    if (idx >= BB * INNER) return;
    int c = idx & (INNER - 1);
    float xm = 0.f;
    #pragma unroll
    for (int s = 0; s < 4; s++) xm += xm_part[(size_t)s * BB * INNER + idx];
    const float* cs = conv_state + (size_t)idx * 3;
    float s0 = cs[0], s1 = cs[1], s2 = cs[2];
    const float* w = conv_w + c * 4;
    float xc = s0*w[0] + s1*w[1] + s2*w[2] + xm*w[3] + conv_b[c];
    float* nc = out + CONV_OFF + (size_t)idx * 3;
    nc[0] = s1; nc[1] = s2; nc[2] = xm;
    g_xmc[idx] = xc / (1.f + expf(-xc));
}

// ============================================================================
// Gates
// ============================================================================
__global__ __launch_bounds__(256) void gate_kernel(
    const float* __restrict__ Wi, const float* __restrict__ bi,
    const float* __restrict__ Wf, const float* __restrict__ bf,
    const float* __restrict__ max_state,
    float* __restrict__ out)
{
    __shared__ float ri[256], rf[256];
    int bh = blockIdx.x;
    int h = bh & (NH - 1);
    int b = bh >> 3;
    int tid = threadIdx.x;
    const float4* q4  = (const float4*)(g_qkv + (size_t)b * K3);
    const float4* wi4 = (const float4*)(Wi + (size_t)h * K3);
    const float4* wf4 = (const float4*)(Wf + (size_t)h * K3);
    float si = 0.f, sf = 0.f;
    #pragma unroll
    for (int r = 0; r < K3/4/256; r++) {
        int j = tid + r * 256;
        float4 q = q4[j], a = wi4[j], f = wf4[j];
        si += q.x*a.x + q.y*a.y + q.z*a.z + q.w*a.w;
        sf += q.x*f.x + q.y*f.y + q.z*f.z + q.w*f.w;
    }
    ri[tid] = si; rf[tid] = sf; __syncthreads();
    for (int st = 128; st > 0; st >>= 1) {
        if (tid < st) { ri[tid] += ri[tid+st]; rf[tid] += rf[tid+st]; }
        __syncthreads();
    }
    if (tid == 0) {
        float ig = CAP * tanhf((ri[0] + bi[h]) / CAP);
        float fg = CAP * tanhf((rf[0] + bf[h]) / CAP);
        float lf = (fg >= 0.f) ? -log1pf(expf(-fg)) : (fg - log1pf(expf(fg)));
        float m_old = max_state[bh];
        float m_new = fmaxf(ig, m_old + lf);
        g_ig[bh] = expf(ig - m_new);
        g_fg[bh] = expf(lf + m_old - m_new);
        out[MAX_OFF + bh] = m_new;
    }
}

// ============================================================================
// Cell stream: grid = 4 chunks x 256 bh; 256 threads.
// ============================================================================
__global__ __launch_bounds__(256) void cell_stream(
    const float* __restrict__ cell_state,
    float* __restrict__ out)
{
    __shared__ float qsm[128], ksm[128];
    __shared__ float part[2][HEAD];

    const int bid = blockIdx.x;
    const int bh = bid >> 2;
    const int ch = bid & 3;
    const int h = bh & (NH - 1);
    const int b = bh >> 3;
    const int tid = threadIdx.x;

    const float* qrow = g_qkv + (size_t)b * K3 + h * HEAD;
    const float* krow = qrow + INNER;
    const float* vrow = qrow + 2 * INNER;
    const int d0 = ch * 128;

    if (tid < 128) {
        qsm[tid] = qrow[d0 + tid];
        ksm[tid] = krow[d0 + tid] * KSCALE;
    }
    __syncthreads();

    const float ig = g_ig[bh];
    const float fg = g_fg[bh];

    const int ct = tid & 127;
    const int rg = tid >> 7;
    const int e0 = ct * 4;
    float4 v = *(const float4*)(vrow + e0);
    float4 iv = make_float4(ig*v.x, ig*v.y, ig*v.z, ig*v.w);

    const float* cin  = cell_state + (size_t)bh * HEAD * HEAD;
    float*       cout = out + CELL_OFF + (size_t)bh * HEAD * HEAD;

    float4 nacc = make_float4(0.f, 0.f, 0.f, 0.f);
    #pragma unroll 8
    for (int dd = rg; dd < 128; dd += 2) {
        int d = d0 + dd;
        float4 cv = *(const float4*)(cin + (size_t)d * HEAD + e0);
        float kd = ksm[dd];
        float4 c;
        c.x = fmaf(fg, cv.x, kd * iv.x);
        c.y = fmaf(fg, cv.y, kd * iv.y);
        c.z = fmaf(fg, cv.z, kd * iv.z);
        c.w = fmaf(fg, cv.w, kd * iv.w);
        *(float4*)(cout + (size_t)d * HEAD + e0) = c;
        float qd = qsm[dd];
        nacc.x = fmaf(qd, c.x, nacc.x);
        nacc.y = fmaf(qd, c.y, nacc.y);
        nacc.z = fmaf(qd, c.z, nacc.z);
        nacc.w = fmaf(qd, c.w, nacc.w);
    }
    *(float4*)&part[rg][e0] = nacc;
    __syncthreads();
    if (tid < 128) {
        float4 p0 = *(const float4*)&part[0][e0];
        float4 p1 = *(const float4*)&part[1][e0];
        float4 s = make_float4(p0.x+p1.x, p0.y+p1.y, p0.z+p1.z, p0.w+p1.w);
        *(float4*)(g_numer + (size_t)bid * HEAD + e0) = s;
    }
}

// ============================================================================
// Cell epilogue: norm_new + qn + denom + GroupNorm + gating -> h
// (x_gate split-4 reduce fused)
// ============================================================================
__global__ __launch_bounds__(512) void cell_epi(
    const float* __restrict__ norm_state,
    const float* __restrict__ gn_w, const float* __restrict__ gn_b,
    const float* __restrict__ skip_w,
    const float* __restrict__ xg_part,
    float* __restrict__ out)
{
    __shared__ float red[512];
    const int bh = blockIdx.x;
    const int h = bh & (NH - 1);
    const int b = bh >> 3;
    const int tid = threadIdx.x;

    const float* qrow = g_qkv + (size_t)b * K3 + h * HEAD;
    const float* krow = qrow + INNER;
    float q = qrow[tid];
    float k = krow[tid] * KSCALE;

    const float ig = g_ig[bh];
    const float fg = g_fg[bh];
    const float m_new = out[MAX_OFF + bh];

    float num = g_numer[(size_t)(bh*4+0) * HEAD + tid]
              + g_numer[(size_t)(bh*4+1) * HEAD + tid]
              + g_numer[(size_t)(bh*4+2) * HEAD + tid]
              + g_numer[(size_t)(bh*4+3) * HEAD + tid];

    float nn = fmaf(fg, norm_state[(size_t)bh * HEAD + tid], ig * k);
    out[NORM_OFF + (size_t)bh * HEAD + tid] = nn;

    red[tid] = q * nn; __syncthreads();
    for (int st = 256; st > 0; st >>= 1) {
        if (tid < st) red[tid] += red[tid+st];
        __syncthreads();
    }
    float qn = red[0]; __syncthreads();
    float denom = fmaxf(fabsf(qn), expf(-m_new)) + EPS;
    float o = num / denom;

    red[tid] = o; __syncthreads();
    for (int st = 256; st > 0; st >>= 1) {
        if (tid < st) red[tid] += red[tid+st];
        __syncthreads();
    }
    float mu = red[0] / (float)HEAD; __syncthreads();
    float dv = o - mu;
    red[tid] = dv * dv; __syncthreads();
    for (int st = 256; st > 0; st >>= 1) {
        if (tid < st) red[tid] += red[tid+st];
        __syncthreads();
    }
    float rstd = rsqrtf(red[0] / (float)HEAD + GN_EPS);

    int c = h * HEAD + tid;
    size_t gidx = (size_t)b * INNER + c;
    float xg = 0.f;
    #pragma unroll
    for (int s = 0; s < 4; s++) xg += xg_part[(size_t)s * BB * INNER + gidx];
    float og = fmaf(dv * rstd, gn_w[c], gn_b[c]);
    float sg = xg / (1.f + expf(-xg));
    g_h[gidx] = (og + skip_w[c] * g_xmc[gidx]) * sg;
}

// ============================================================================
extern "C" void kernel_launch(void* const* d_in, const int* in_sizes, int n_in,
                              void* d_out, int out_size)
{
    const float* x          = (const float*)d_in[0];
    const float* conv_state = (const float*)d_in[1];
    const float* cell_state = (const float*)d_in[2];
    const float* norm_state = (const float*)d_in[3];
    const float* max_state  = (const float*)d_in[4];
    const float* rms_w      = (const float*)d_in[5];
    const float* Wx         = (const float*)d_in[6];
    const float* Wg         = (const float*)d_in[7];
    const float* Wqkv       = (const float*)d_in[8];
    const float* conv_w     = (const float*)d_in[9];
    const float* conv_b     = (const float*)d_in[10];
    const float* Wi         = (const float*)d_in[11];
    const float* bi         = (const float*)d_in[12];
    const float* Wf         = (const float*)d_in[13];
    const float* bf         = (const float*)d_in[14];
    const float* gn_w       = (const float*)d_in[15];
    const float* gn_b       = (const float*)d_in[16];
    const float* Wdown      = (const float*)d_in[17];
    const float* skip_w     = (const float*)d_in[18];
    float* out = (float*)d_out;

    float* pxn;   cudaGetSymbolAddress((void**)&pxn,   g_xn);
    float* pxmc;  cudaGetSymbolAddress((void**)&pxmc,  g_xmc);
    float* pqkv;  cudaGetSymbolAddress((void**)&pqkv,  g_qkv);
    float* ph;    cudaGetSymbolAddress((void**)&ph,    g_h);
    float* ppart; cudaGetSymbolAddress((void**)&ppart, g_part);

    // Wg partials: beyond QKV's 4-split region [0, 4*BB*K3)
    float* pp2 = ppart + (size_t)4 * BB * K3;

    cudaFuncSetAttribute(mma_gemm, cudaFuncAttributeMaxDynamicSharedMemorySize,
                         SMEM_MMA);

    // 1) rmsnorm
    rmsnorm_kernel<<<BB, 256>>>(x, rms_w);

    // 2) x_mlstm & x_gate tensor-core GEMM, split-K 4: grid (32+32, 4) = 256
    mma_gemm<<<dim3(64, 4), 256, SMEM_MMA>>>(pxn, Wx, ppart, INNER,
                                             Wg, pp2, INNER, 32, HID, HID/4);

    // 3) conv (fused xm split-4 reduce) + silu + new_conv_state
    conv_kernel<<<(BB*INNER)/256, 256>>>(conv_state, conv_w, conv_b, ppart, out);

    // 4) qkv = xmc @ Wqkv^T, split-K 4: grid (96, 4) = 384
    mma_gemm<<<dim3(96, 4), 256, SMEM_MMA>>>(pxmc, Wqkv, ppart, K3,
                                             Wqkv, ppart, K3, 96, INNER, INNER/4);
    reduce_split_t<4><<<(BB*K3/4)/256, 256>>>(ppart, BB*K3, nullptr, pqkv);

    // 5) gates
    gate_kernel<<<BB*NH, 256>>>(Wi, bi, Wf, bf, max_state, out);

    // 6) cell stream: 1024 blocks
    cell_stream<<<BB*NH*4, 256>>>(cell_state, out);

    // 7) cell epilogue (fused xg reduce) -> h
    cell_epi<<<BB*NH, 512>>>(norm_state, gn_w, gn_b, skip_w, pp2, out);

    // 8) y = h @ Wdown^T + x, split-K 8: grid (16, 8) = 128
    mma_gemm<<<dim3(16, 8), 256, SMEM_MMA>>>(ph, Wdown, ppart, HID,
                                             Wdown, ppart, HID, 16, INNER, INNER/8);
    reduce_split_t<8><<<(BB*HID/4)/256, 256>>>(ppart, BB*HID, x, out + Y_OFF);
}